// round 5
// baseline (speedup 1.0000x reference)
#include <cuda_runtime.h>
#include <stdint.h>

// Problem constants (fixed instance: features [2048,2,256] f32, labels [2048] i64)
#define NR   4096          // N = 2048 * 2 views
#define DIM  256
#define TEMP_INV 20.0f     // 1/0.05
#define MARGIN_C 0.2f
#define TOPK 1433          // int(4096 * 0.35)
#define LOSS_SCALE (-(0.05f/0.07f))

// Scratch (static __device__ globals: allocation-free per harness rules)
__device__ __align__(16) float g_fN[NR * DIM];          // normalized features, row-major
__device__ __align__(16) float g_fT[DIM * NR];          // transposed (k-major) for coalesced GEMM B-reads
__device__ __align__(16) float g_S[(size_t)NR * NR];    // raw dot products (64 MB, L2-resident)
__device__ int g_lab[NR];

// ---------------------------------------------------------------------------
// packed f32x2 FMA (Blackwell): 2 fp32 FMAs per instruction (FFMA2)
// ---------------------------------------------------------------------------
__device__ __forceinline__ unsigned long long ffma2(unsigned long long a,
                                                    unsigned long long b,
                                                    unsigned long long c) {
    unsigned long long d;
    asm("fma.rn.f32x2 %0, %1, %2, %3;" : "=l"(d) : "l"(a), "l"(b), "l"(c));
    return d;
}

// ---------------------------------------------------------------------------
// Kernel 1: L2-normalize rows, build row-major + k-major copies, labels, zero out
// grid 4096, block 256 (one block per row, one thread per element)
// ---------------------------------------------------------------------------
__global__ void prep_kernel(const float* __restrict__ feat,
                            const long long* __restrict__ labels,
                            float* __restrict__ out) {
    __shared__ float red[DIM];
    int i = blockIdx.x, t = threadIdx.x;
    float v = feat[i * DIM + t];
    red[t] = v * v;
    __syncthreads();
    for (int s = 128; s > 0; s >>= 1) {
        if (t < s) red[t] += red[t + s];
        __syncthreads();
    }
    float inv = 1.0f / fmaxf(sqrtf(red[0]), 1e-12f);
    float nv = v * inv;
    g_fN[i * DIM + t] = nv;
    g_fT[t * NR + i] = nv;
    if (t == 0) {
        g_lab[i] = (int)labels[i >> 1];   // repeat_interleave of labels over 2 views
        if (i == 0) *out = 0.0f;
    }
}

// ---------------------------------------------------------------------------
// Kernel 2: S = fN * fN^T via packed f32x2 FMA.
// BI=16 rows per CTA, 256 threads, each thread computes 16 columns (4 groups x float4).
// A-rows cached in smem as duplicated-pair u64 (no per-iter pack), B read as
// 16B vectors from k-major g_fT (fully coalesced).
// ---------------------------------------------------------------------------
#define BI 16
__global__ void __launch_bounds__(256, 2) gemm_kernel() {
    __shared__ unsigned long long a2s[BI][DIM];   // 32 KB: each entry = (v,v) packed
    const int i0 = blockIdx.x * BI;
    const int t  = threadIdx.x;

    for (int x = t; x < BI * DIM; x += 256) {
        int r = x >> 8, kk = x & 255;
        unsigned u = __float_as_uint(g_fN[(i0 + r) * DIM + kk]);
        a2s[r][kk] = (unsigned long long)u * 0x100000001ull;   // u | (u<<32)
    }
    __syncthreads();

    const ulonglong2* fT2 = reinterpret_cast<const ulonglong2*>(g_fT);

    for (int g = 0; g < 4; ++g) {
        const int base = g * 256 + t;         // index in units of 4 floats within a k-row
        unsigned long long acc[BI][2];
        #pragma unroll
        for (int r = 0; r < BI; ++r) { acc[r][0] = 0ull; acc[r][1] = 0ull; }

        #pragma unroll 4
        for (int kk = 0; kk < DIM; ++kk) {
            ulonglong2 b = fT2[kk * (NR / 4) + base];   // 4 consecutive j columns
            #pragma unroll
            for (int r = 0; r < BI; ++r) {
                unsigned long long a = a2s[r][kk];
                acc[r][0] = ffma2(a, b.x, acc[r][0]);
                acc[r][1] = ffma2(a, b.y, acc[r][1]);
            }
        }

        const int j0 = g * 1024 + t * 4;
        #pragma unroll
        for (int r = 0; r < BI; ++r) {
            float4 o;
            o.x = __uint_as_float((unsigned)(acc[r][0]));
            o.y = __uint_as_float((unsigned)(acc[r][0] >> 32));
            o.z = __uint_as_float((unsigned)(acc[r][1]));
            o.w = __uint_as_float((unsigned)(acc[r][1] >> 32));
            *reinterpret_cast<float4*>(&g_S[(size_t)(i0 + r) * NR + j0]) = o;
        }
    }
}

// ---------------------------------------------------------------------------
// Kernel 3: per-row loss. One CTA (256 threads) per row.
//   - logits l = dot/T, shift by row max
//   - negatives get -MARGIN; order-preserving uint key (0 == positive sentinel)
//   - exact k-th-largest negative via 4-pass MSB radix select (ties handled
//     by rank count, matching jax top_k exactly since equal keys => equal exp)
//   - Z = sum_pos exp + sum_topk_neg exp; loss_i accumulated atomically
// ---------------------------------------------------------------------------
__global__ void __launch_bounds__(256) loss_kernel(float* __restrict__ out) {
    __shared__ float sv[NR];          // shifted (margin-applied) logits
    __shared__ unsigned ku[NR];       // order keys; 0 => positive
    __shared__ float red[256];
    __shared__ unsigned hist[256];
    __shared__ unsigned sh_prefix;
    __shared__ int sh_kr;

    const int i = blockIdx.x, t = threadIdx.x;

    // load row, scale by 1/T, track local max
    float lm = -1e30f;
    for (int j = t; j < NR; j += 256) {
        float l = g_S[(size_t)i * NR + j] * TEMP_INV;
        sv[j] = l;
        lm = fmaxf(lm, l);
    }
    red[t] = lm; __syncthreads();
    for (int s = 128; s > 0; s >>= 1) { if (t < s) red[t] = fmaxf(red[t], red[t + s]); __syncthreads(); }
    const float M = red[0];
    __syncthreads();

    const int labi = g_lab[i];
    float cneg = 0.f;
    for (int j = t; j < NR; j += 256) {
        float a = sv[j] - M;
        unsigned key = 0u;
        if (g_lab[j] != labi) {                 // negative (diag is always positive)
            a -= MARGIN_C;
            unsigned b = __float_as_uint(a);
            key = (b & 0x80000000u) ? ~b : (b | 0x80000000u);  // order-preserving; finite neg logit => key > 0
            cneg += 1.f;
        }
        sv[j] = a;
        ku[j] = key;
    }
    __syncthreads();
    red[t] = cneg; __syncthreads();
    for (int s = 128; s > 0; s >>= 1) { if (t < s) red[t] += red[t + s]; __syncthreads(); }
    const int count_neg = (int)red[0];
    __syncthreads();

    const bool selAll = (count_neg <= TOPK);
    unsigned keystar = 0; int rsel = 0;
    if (!selAll) {
        if (t == 0) { sh_prefix = 0u; sh_kr = TOPK; }
        __syncthreads();
        for (int shift = 24; shift >= 0; shift -= 8) {
            hist[t] = 0u; __syncthreads();
            const unsigned pfx = sh_prefix;
            for (int j = t; j < NR; j += 256) {
                unsigned key = ku[j];
                bool match = (shift == 24) || ((key >> (shift + 8)) == (pfx >> (shift + 8)));
                if (match) atomicAdd(&hist[(key >> shift) & 255u], 1u);
            }
            __syncthreads();
            if (t == 0) {
                int kr = sh_kr, cum = 0, d = 0;
                for (int dig = 255; dig >= 0; --dig) {
                    int c = (int)hist[dig];
                    if (cum + c >= kr) { d = dig; sh_kr = kr - cum; break; }
                    cum += c;
                }
                sh_prefix = pfx | ((unsigned)d << shift);
            }
            __syncthreads();
        }
        keystar = sh_prefix;
        rsel = sh_kr;           // how many of the exactly-keystar ties are in the top-k
    }

    // sums: positives (key==0) and selected negatives (key > keystar)
    float s_ep = 0.f, s_lp = 0.f, s_cp = 0.f, s_en = 0.f;
    for (int j = t; j < NR; j += 256) {
        float a = sv[j];
        unsigned key = ku[j];
        if (key == 0u) {
            s_ep += __expf(a); s_lp += a; s_cp += 1.f;
        } else if (selAll || key > keystar) {
            s_en += __expf(a);
        }
    }
    // 4 sequential block reductions
    red[t] = s_ep; __syncthreads();
    for (int s = 128; s > 0; s >>= 1) { if (t < s) red[t] += red[t + s]; __syncthreads(); }
    float T_ep = red[0]; __syncthreads();
    red[t] = s_lp; __syncthreads();
    for (int s = 128; s > 0; s >>= 1) { if (t < s) red[t] += red[t + s]; __syncthreads(); }
    float T_lp = red[0]; __syncthreads();
    red[t] = s_cp; __syncthreads();
    for (int s = 128; s > 0; s >>= 1) { if (t < s) red[t] += red[t + s]; __syncthreads(); }
    float T_cp = red[0]; __syncthreads();
    red[t] = s_en; __syncthreads();
    for (int s = 128; s > 0; s >>= 1) { if (t < s) red[t] += red[t + s]; __syncthreads(); }
    float T_en = red[0];

    if (t == 0) {
        if (!selAll) {
            unsigned b = (keystar & 0x80000000u) ? (keystar & 0x7FFFFFFFu) : ~keystar;
            T_en += (float)rsel * __expf(__uint_as_float(b));
        }
        float Z = T_ep + T_en;
        float logZ = logf(Z + 1e-12f);
        float mlpp = (T_lp - T_cp * logZ) / (T_cp + 1e-12f);
        float loss = LOSS_SCALE * mlpp;
        atomicAdd(out, loss * (1.0f / (float)NR));
    }
}

// ---------------------------------------------------------------------------
extern "C" void kernel_launch(void* const* d_in, const int* in_sizes, int n_in,
                              void* d_out, int out_size) {
    const float* feat = (const float*)d_in[0];          // [2048, 2, 256] f32
    const long long* labels = (const long long*)d_in[1];// [2048] i64
    float* out = (float*)d_out;

    prep_kernel<<<NR, 256>>>(feat, labels, out);
    gemm_kernel<<<NR / BI, 256>>>();
    loss_kernel<<<NR, 256>>>(out);
}

// round 11
// speedup vs baseline: 1.9739x; 1.9739x over previous
#include <cuda_runtime.h>
#include <cuda_bf16.h>
#include <stdint.h>

// Fixed instance: features [2048,2,256] f32, labels [2048] i64 -> scalar f32
#define NR   4096
#define DIM  256
#define TEMP_INV 20.0f
#define MARGIN_C 0.2f
#define TOPK 1433               // int(4096 * 0.35)
#define LOSS_SCALE (-(0.05f/0.07f))

// Scratch (__device__ globals: allocation-free per harness rules)
__device__ __align__(16) __nv_bfloat16 g_hi[NR * DIM];   // bf16 high part of normalized features
__device__ __align__(16) __nv_bfloat16 g_lo[NR * DIM];   // bf16 low  part (residual)
__device__ __align__(16) float g_S[(size_t)NR * NR];     // similarity matrix (64 MB, L2-resident)
__device__ __align__(16) int g_lab[NR];

__device__ __forceinline__ uint32_t smem_u32(const void* p) {
    uint32_t r;
    asm("{ .reg .u64 t; cvta.to.shared.u64 t, %1; cvt.u32.u64 %0, t; }" : "=r"(r) : "l"(p));
    return r;
}

// ldmatrix x4 (sm_75+ PTX, works on compute_103 virtual arch)
__device__ __forceinline__ void ldsm4(uint32_t* r, uint32_t a) {
    asm volatile("ldmatrix.sync.aligned.m8n8.x4.shared.b16 {%0,%1,%2,%3}, [%4];"
                 : "=r"(r[0]), "=r"(r[1]), "=r"(r[2]), "=r"(r[3]) : "r"(a));
}
// bf16 HMMA m16n8k16 (sm_80+ PTX)
__device__ __forceinline__ void mma16816(float* c, const uint32_t* a, const uint32_t* b) {
    asm volatile("mma.sync.aligned.m16n8k16.row.col.f32.bf16.bf16.f32 "
                 "{%0,%1,%2,%3}, {%4,%5,%6,%7}, {%8,%9}, {%0,%1,%2,%3};"
                 : "+f"(c[0]), "+f"(c[1]), "+f"(c[2]), "+f"(c[3])
                 : "r"(a[0]), "r"(a[1]), "r"(a[2]), "r"(a[3]), "r"(b[0]), "r"(b[1]));
}

// ===========================================================================
// Kernel 1: normalize + bf16 hi/lo split + labels + zero out
// ===========================================================================
__global__ void prep_kernel(const float* __restrict__ feat,
                            const long long* __restrict__ labels,
                            float* __restrict__ out) {
    __shared__ float red[256];
    int i = blockIdx.x, t = threadIdx.x;
    float v = feat[i * DIM + t];
    red[t] = v * v;
    __syncthreads();
    for (int s = 128; s > 0; s >>= 1) { if (t < s) red[t] += red[t + s]; __syncthreads(); }
    float nv = v / fmaxf(sqrtf(red[0]), 1e-12f);
    __nv_bfloat16 h = __float2bfloat16(nv);
    g_hi[i * DIM + t] = h;
    g_lo[i * DIM + t] = __float2bfloat16(nv - __bfloat162float(h));
    if (t == 0) {
        g_lab[i] = (int)labels[i >> 1];
        if (i == 0) *out = 0.0f;
    }
}

// ===========================================================================
// Kernel 2: S = fN*fN^T via mma.sync bf16 split (hi*hi + hi*lo + lo*hi).
// CTA 128x128, 8 warps (warp tile 32x64), K chunks of 64.
// smem: 4 tiles 128x64 bf16 (Ahi,Alo,Bhi,Blo) = 64 KB, 16B-XOR swizzle.
// ===========================================================================
#define SM_AHI 0
#define SM_ALO 16384
#define SM_BHI 32768
#define SM_BLO 49152
#define SMEM_GEMM 65536

__global__ void __launch_bounds__(256) gemm_kernel() {
    extern __shared__ char sm[];
    const uint32_t sb = smem_u32(sm);
    const int t = threadIdx.x, wid = t >> 5, l = t & 31;
    const int i0 = blockIdx.x * 128, j0 = blockIdx.y * 128;
    const int wm = wid & 3, wn = wid >> 2;      // warp tile: rows wm*32, cols wn*64

    float c[2][8][4];
    #pragma unroll
    for (int mi = 0; mi < 2; ++mi)
        #pragma unroll
        for (int ni = 0; ni < 8; ++ni)
            #pragma unroll
            for (int q = 0; q < 4; ++q) c[mi][ni][q] = 0.f;

    for (int kc = 0; kc < 4; ++kc) {
        __syncthreads();                        // previous chunk's reads done
        // Load 4 tiles (each: 128 rows x 64 bf16 = 128B/row), XOR-swizzled 16B chunks
        #pragma unroll
        for (int it = 0; it < 4; ++it) {
            int idx = t + it * 256;             // 0..1023
            int r = idx >> 3, c16 = idx & 7;
            uint32_t dst = (uint32_t)(r * 128 + ((c16 ^ (r & 7)) << 4));
            int gsrc = (i0 + r) * DIM + kc * 64 + c16 * 8;
            int gsrcB = (j0 + r) * DIM + kc * 64 + c16 * 8;
            *reinterpret_cast<uint4*>(sm + SM_AHI + dst) = *reinterpret_cast<const uint4*>(&g_hi[gsrc]);
            *reinterpret_cast<uint4*>(sm + SM_ALO + dst) = *reinterpret_cast<const uint4*>(&g_lo[gsrc]);
            *reinterpret_cast<uint4*>(sm + SM_BHI + dst) = *reinterpret_cast<const uint4*>(&g_hi[gsrcB]);
            *reinterpret_cast<uint4*>(sm + SM_BLO + dst) = *reinterpret_cast<const uint4*>(&g_lo[gsrcB]);
        }
        __syncthreads();

        #pragma unroll
        for (int ks = 0; ks < 4; ++ks) {
            // ldmatrix offsets (bytes within a tile)
            uint32_t offA[2], offB[4];
            #pragma unroll
            for (int mi = 0; mi < 2; ++mi) {
                int R = wm * 32 + mi * 16 + (l & 7) + ((l >> 3) & 1) * 8;
                int c16 = 2 * ks + (l >> 4);
                offA[mi] = (uint32_t)(R * 128 + ((c16 ^ (R & 7)) << 4));
            }
            #pragma unroll
            for (int nq = 0; nq < 4; ++nq) {
                int R = wn * 64 + nq * 16 + (l & 7) + ((l >> 4) & 1) * 8;
                int c16 = 2 * ks + ((l >> 3) & 1);
                offB[nq] = (uint32_t)(R * 128 + ((c16 ^ (R & 7)) << 4));
            }
            uint32_t ah[2][4], al[2][4], bh[4][4], bl[4][4];
            #pragma unroll
            for (int mi = 0; mi < 2; ++mi) {
                ldsm4(ah[mi], sb + SM_AHI + offA[mi]);
                ldsm4(al[mi], sb + SM_ALO + offA[mi]);
            }
            #pragma unroll
            for (int nq = 0; nq < 4; ++nq) {
                ldsm4(bh[nq], sb + SM_BHI + offB[nq]);
                ldsm4(bl[nq], sb + SM_BLO + offB[nq]);
            }
            // 3 passes: hi*hi, hi*lo, lo*hi
            #pragma unroll
            for (int mi = 0; mi < 2; ++mi)
                #pragma unroll
                for (int ni = 0; ni < 8; ++ni) {
                    const int nq = ni >> 1, s2 = (ni & 1) * 2;
                    mma16816(c[mi][ni], ah[mi], &bh[nq][s2]);
                    mma16816(c[mi][ni], ah[mi], &bl[nq][s2]);
                    mma16816(c[mi][ni], al[mi], &bh[nq][s2]);
                }
        }
    }

    // Epilogue: write 128x128 f32 tile
    const int gid = l >> 2, tig = l & 3;
    #pragma unroll
    for (int mi = 0; mi < 2; ++mi) {
        #pragma unroll
        for (int ni = 0; ni < 8; ++ni) {
            int rg = i0 + wm * 32 + mi * 16 + gid;
            int cg = j0 + wn * 64 + ni * 8 + 2 * tig;
            float2 v0 = make_float2(c[mi][ni][0], c[mi][ni][1]);
            float2 v1 = make_float2(c[mi][ni][2], c[mi][ni][3]);
            *reinterpret_cast<float2*>(&g_S[(size_t)rg * NR + cg]) = v0;
            *reinterpret_cast<float2*>(&g_S[(size_t)(rg + 8) * NR + cg]) = v1;
        }
    }
}

// ===========================================================================
// Kernel 3: per-row loss. 256 threads/CTA, 16 elements/thread in registers.
// match_any-aggregated histogram + parallel warp-shuffle suffix scan.
// ===========================================================================
__global__ void __launch_bounds__(256) loss_kernel(float* __restrict__ out) {
    __shared__ float smax[8];
    __shared__ int   swc[8];
    __shared__ unsigned hist[256];
    __shared__ unsigned wt[8];
    __shared__ unsigned s_sel[2];
    __shared__ float r4[4][8];

    const int i = blockIdx.x, t = threadIdx.x, lane = t & 31, warp = t >> 5;
    const float4* S4 = reinterpret_cast<const float4*>(g_S + (size_t)i * NR);
    const int4* L4 = reinterpret_cast<const int4*>(g_lab);
    const int labi = g_lab[i];

    float a[16]; int lb[16];
    float m = -1e30f;
    #pragma unroll
    for (int c = 0; c < 4; ++c) {
        float4 v = S4[c * 256 + t];
        int4 l = L4[c * 256 + t];
        a[c*4+0] = v.x * TEMP_INV; a[c*4+1] = v.y * TEMP_INV;
        a[c*4+2] = v.z * TEMP_INV; a[c*4+3] = v.w * TEMP_INV;
        lb[c*4+0] = l.x; lb[c*4+1] = l.y; lb[c*4+2] = l.z; lb[c*4+3] = l.w;
        #pragma unroll
        for (int q = 0; q < 4; ++q) m = fmaxf(m, a[c*4+q]);
    }
    #pragma unroll
    for (int off = 16; off > 0; off >>= 1) m = fmaxf(m, __shfl_xor_sync(0xFFFFFFFFu, m, off));
    if (lane == 0) smax[warp] = m;
    __syncthreads();
    float M = smax[0];
    #pragma unroll
    for (int w = 1; w < 8; ++w) M = fmaxf(M, smax[w]);

    unsigned key[16];
    int cneg = 0;
    #pragma unroll
    for (int e = 0; e < 16; ++e) {
        float x = a[e] - M;
        if (lb[e] != labi) {
            x -= MARGIN_C;
            unsigned b = __float_as_uint(x);
            key[e] = (b & 0x80000000u) ? ~b : (b | 0x80000000u);
            cneg++;
        } else key[e] = 0u;
        a[e] = x;
    }
    #pragma unroll
    for (int off = 16; off > 0; off >>= 1) cneg += __shfl_xor_sync(0xFFFFFFFFu, cneg, off);
    if (lane == 0) swc[warp] = cneg;
    __syncthreads();
    int count_neg = 0;
    #pragma unroll
    for (int w = 0; w < 8; ++w) count_neg += swc[w];

    const bool selAll = (count_neg <= TOPK);
    unsigned pfx = 0, kr = TOPK;
    if (!selAll) {
        #pragma unroll
        for (int shift = 24; shift >= 0; shift -= 8) {
            hist[t] = 0u;
            __syncthreads();
            #pragma unroll
            for (int e = 0; e < 16; ++e) {
                unsigned k = key[e];
                bool match = (k != 0u) &&
                             ((shift == 24) || ((k >> (shift + 8)) == (pfx >> (shift + 8))));
                unsigned dig = (k >> shift) & 255u;
                unsigned mv = match ? dig : 0xFFFFFFFFu;
                unsigned mk = __match_any_sync(0xFFFFFFFFu, mv);
                if (match && lane == (__ffs(mk) - 1))
                    atomicAdd(&hist[dig], (unsigned)__popc(mk));
            }
            __syncthreads();
            unsigned c = hist[t];
            unsigned v = c;
            #pragma unroll
            for (int off = 1; off < 32; off <<= 1) {
                unsigned u = __shfl_down_sync(0xFFFFFFFFu, v, off);
                if (lane + off < 32) v += u;
            }
            if (lane == 0) wt[warp] = v;     // warp-total
            __syncthreads();
            unsigned hi = 0;
            #pragma unroll
            for (int w = 0; w < 8; ++w) if (w > warp) hi += wt[w];
            unsigned suf_in = v + hi, suf_ex = suf_in - c;
            if (suf_ex < kr && suf_in >= kr) { s_sel[0] = (unsigned)t; s_sel[1] = kr - suf_ex; }
            __syncthreads();
            pfx |= s_sel[0] << shift;
            kr = s_sel[1];
            __syncthreads();
        }
    }
    const unsigned keystar = pfx;
    const unsigned rsel = kr;

    float ep = 0.f, lp = 0.f, cp = 0.f, en = 0.f;
    #pragma unroll
    for (int e = 0; e < 16; ++e) {
        if (key[e] == 0u) { float ex = __expf(a[e]); ep += ex; lp += a[e]; cp += 1.f; }
        else if (selAll || key[e] > keystar) en += __expf(a[e]);
    }
    #pragma unroll
    for (int off = 16; off > 0; off >>= 1) {
        ep += __shfl_xor_sync(0xFFFFFFFFu, ep, off);
        lp += __shfl_xor_sync(0xFFFFFFFFu, lp, off);
        cp += __shfl_xor_sync(0xFFFFFFFFu, cp, off);
        en += __shfl_xor_sync(0xFFFFFFFFu, en, off);
    }
    if (lane == 0) { r4[0][warp] = ep; r4[1][warp] = lp; r4[2][warp] = cp; r4[3][warp] = en; }
    __syncthreads();
    if (t == 0) {
        float Tep = 0, Tlp = 0, Tcp = 0, Ten = 0;
        #pragma unroll
        for (int w = 0; w < 8; ++w) { Tep += r4[0][w]; Tlp += r4[1][w]; Tcp += r4[2][w]; Ten += r4[3][w]; }
        if (!selAll) {
            unsigned b = (keystar & 0x80000000u) ? (keystar & 0x7FFFFFFFu) : ~keystar;
            Ten += (float)rsel * __expf(__uint_as_float(b));
        }
        float Z = Tep + Ten;
        float logZ = logf(Z + 1e-12f);
        float mlpp = (Tlp - Tcp * logZ) / (Tcp + 1e-12f);
        atomicAdd(out, LOSS_SCALE * mlpp * (1.0f / (float)NR));
    }
}

// ===========================================================================
extern "C" void kernel_launch(void* const* d_in, const int* in_sizes, int n_in,
                              void* d_out, int out_size) {
    const float* feat = (const float*)d_in[0];
    const long long* labels = (const long long*)d_in[1];
    float* out = (float*)d_out;

    cudaFuncSetAttribute(gemm_kernel, cudaFuncAttributeMaxDynamicSharedMemorySize, SMEM_GEMM);

    prep_kernel<<<NR, 256>>>(feat, labels, out);
    gemm_kernel<<<dim3(32, 32, 1), 256, SMEM_GEMM>>>();
    loss_kernel<<<NR, 256>>>(out);
}

// round 15
// speedup vs baseline: 2.1728x; 1.1008x over previous
#include <cuda_runtime.h>
#include <cuda_bf16.h>
#include <stdint.h>

// Fixed instance: features [2048,2,256] f32, labels [2048] i64 -> scalar f32
#define NR   4096
#define DIM  256
#define TEMP_INV 20.0f
#define MARGIN_C 0.2f
#define TOPK 1433               // int(4096 * 0.35)
#define LOSS_SCALE (-(0.05f/0.07f))

// Scratch (__device__ globals: allocation-free per harness rules)
__device__ __align__(16) __nv_bfloat16 g_hi[NR * DIM];   // bf16 high part of normalized features
__device__ __align__(16) __nv_bfloat16 g_lo[NR * DIM];   // bf16 low  part (residual)
__device__ __align__(16) float g_S[(size_t)NR * NR];     // similarity matrix (64 MB, L2-resident)
__device__ __align__(16) int g_lab[NR];

__device__ __forceinline__ uint32_t smem_u32(const void* p) {
    uint32_t r;
    asm("{ .reg .u64 t; cvta.to.shared.u64 t, %1; cvt.u32.u64 %0, t; }" : "=r"(r) : "l"(p));
    return r;
}

// ldmatrix x4 (sm_75+ PTX, works on compute_103 virtual arch)
__device__ __forceinline__ void ldsm4(uint32_t* r, uint32_t a) {
    asm volatile("ldmatrix.sync.aligned.m8n8.x4.shared.b16 {%0,%1,%2,%3}, [%4];"
                 : "=r"(r[0]), "=r"(r[1]), "=r"(r[2]), "=r"(r[3]) : "r"(a));
}
// bf16 HMMA m16n8k16 (sm_80+ PTX)
__device__ __forceinline__ void mma16816(float* c, const uint32_t* a, const uint32_t* b) {
    asm volatile("mma.sync.aligned.m16n8k16.row.col.f32.bf16.bf16.f32 "
                 "{%0,%1,%2,%3}, {%4,%5,%6,%7}, {%8,%9}, {%0,%1,%2,%3};"
                 : "+f"(c[0]), "+f"(c[1]), "+f"(c[2]), "+f"(c[3])
                 : "r"(a[0]), "r"(a[1]), "r"(a[2]), "r"(a[3]), "r"(b[0]), "r"(b[1]));
}

// ===========================================================================
// Kernel 1: normalize + bf16 hi/lo split + labels + zero out
// ===========================================================================
__global__ void prep_kernel(const float* __restrict__ feat,
                            const long long* __restrict__ labels,
                            float* __restrict__ out) {
    __shared__ float red[256];
    int i = blockIdx.x, t = threadIdx.x;
    float v = feat[i * DIM + t];
    red[t] = v * v;
    __syncthreads();
    for (int s = 128; s > 0; s >>= 1) { if (t < s) red[t] += red[t + s]; __syncthreads(); }
    float nv = v / fmaxf(sqrtf(red[0]), 1e-12f);
    __nv_bfloat16 h = __float2bfloat16(nv);
    g_hi[i * DIM + t] = h;
    g_lo[i * DIM + t] = __float2bfloat16(nv - __bfloat162float(h));
    if (t == 0) {
        g_lab[i] = (int)labels[i >> 1];
        if (i == 0) *out = 0.0f;
    }
}

// ===========================================================================
// Kernel 2: S = fN*fN^T via mma.sync bf16 split (hi*hi + hi*lo + lo*hi).
// SYMMETRY: only upper-triangle tiles (bj >= bi) computed; off-diagonal tiles
// also write their transpose via a swizzled smem staging pass.
// CTA 128x128, 8 warps (warp tile 32x64), K chunks of 64.
// smem: 4 tiles 128x64 bf16 = 64 KB (reused as 128x128 f32 transpose buffer).
// ===========================================================================
#define SM_AHI 0
#define SM_ALO 16384
#define SM_BHI 32768
#define SM_BLO 49152
#define SMEM_GEMM 65536

// f32 transpose-staging swizzled address (bytes) for element (r, c) of 128x128
__device__ __forceinline__ uint32_t taddr(int r, int c) {
    return (uint32_t)(r * 512 + (((c >> 2) ^ (r & 31)) << 4) + (c & 3) * 4);
}

__global__ void __launch_bounds__(256) gemm_kernel() {
    extern __shared__ char sm[];
    const uint32_t sb = smem_u32(sm);
    const int t = threadIdx.x, wid = t >> 5, l = t & 31;
    const int bi = blockIdx.x, bj = blockIdx.y;
    if (bj < bi) return;                        // lower triangle: mirror of upper
    const int i0 = bi * 128, j0 = bj * 128;
    const int wm = wid & 3, wn = wid >> 2;      // warp tile: rows wm*32, cols wn*64

    float c[2][8][4];
    #pragma unroll
    for (int mi = 0; mi < 2; ++mi)
        #pragma unroll
        for (int ni = 0; ni < 8; ++ni)
            #pragma unroll
            for (int q = 0; q < 4; ++q) c[mi][ni][q] = 0.f;

    for (int kc = 0; kc < 4; ++kc) {
        __syncthreads();                        // previous chunk's reads done
        // Load 4 tiles (each: 128 rows x 64 bf16 = 128B/row), XOR-swizzled 16B chunks
        #pragma unroll
        for (int it = 0; it < 4; ++it) {
            int idx = t + it * 256;             // 0..1023
            int r = idx >> 3, c16 = idx & 7;
            uint32_t dst = (uint32_t)(r * 128 + ((c16 ^ (r & 7)) << 4));
            int gsrc = (i0 + r) * DIM + kc * 64 + c16 * 8;
            int gsrcB = (j0 + r) * DIM + kc * 64 + c16 * 8;
            *reinterpret_cast<uint4*>(sm + SM_AHI + dst) = *reinterpret_cast<const uint4*>(&g_hi[gsrc]);
            *reinterpret_cast<uint4*>(sm + SM_ALO + dst) = *reinterpret_cast<const uint4*>(&g_lo[gsrc]);
            *reinterpret_cast<uint4*>(sm + SM_BHI + dst) = *reinterpret_cast<const uint4*>(&g_hi[gsrcB]);
            *reinterpret_cast<uint4*>(sm + SM_BLO + dst) = *reinterpret_cast<const uint4*>(&g_lo[gsrcB]);
        }
        __syncthreads();

        #pragma unroll
        for (int ks = 0; ks < 4; ++ks) {
            uint32_t offA[2], offB[4];
            #pragma unroll
            for (int mi = 0; mi < 2; ++mi) {
                int R = wm * 32 + mi * 16 + (l & 7) + ((l >> 3) & 1) * 8;
                int c16 = 2 * ks + (l >> 4);
                offA[mi] = (uint32_t)(R * 128 + ((c16 ^ (R & 7)) << 4));
            }
            #pragma unroll
            for (int nq = 0; nq < 4; ++nq) {
                int R = wn * 64 + nq * 16 + (l & 7) + ((l >> 4) & 1) * 8;
                int c16 = 2 * ks + ((l >> 3) & 1);
                offB[nq] = (uint32_t)(R * 128 + ((c16 ^ (R & 7)) << 4));
            }
            uint32_t ah[2][4], al[2][4], bh[4][4], bl[4][4];
            #pragma unroll
            for (int mi = 0; mi < 2; ++mi) {
                ldsm4(ah[mi], sb + SM_AHI + offA[mi]);
                ldsm4(al[mi], sb + SM_ALO + offA[mi]);
            }
            #pragma unroll
            for (int nq = 0; nq < 4; ++nq) {
                ldsm4(bh[nq], sb + SM_BHI + offB[nq]);
                ldsm4(bl[nq], sb + SM_BLO + offB[nq]);
            }
            // 3 passes: hi*hi, hi*lo, lo*hi
            #pragma unroll
            for (int mi = 0; mi < 2; ++mi)
                #pragma unroll
                for (int ni = 0; ni < 8; ++ni) {
                    const int nq = ni >> 1, s2 = (ni & 1) * 2;
                    mma16816(c[mi][ni], ah[mi], &bh[nq][s2]);
                    mma16816(c[mi][ni], ah[mi], &bl[nq][s2]);
                    mma16816(c[mi][ni], al[mi], &bh[nq][s2]);
                }
        }
    }

    // Direct write of 128x128 f32 tile at (i0, j0)
    const int gid = l >> 2, tig = l & 3;
    #pragma unroll
    for (int mi = 0; mi < 2; ++mi) {
        #pragma unroll
        for (int ni = 0; ni < 8; ++ni) {
            int rg = i0 + wm * 32 + mi * 16 + gid;
            int cg = j0 + wn * 64 + ni * 8 + 2 * tig;
            float2 v0 = make_float2(c[mi][ni][0], c[mi][ni][1]);
            float2 v1 = make_float2(c[mi][ni][2], c[mi][ni][3]);
            *reinterpret_cast<float2*>(&g_S[(size_t)rg * NR + cg]) = v0;
            *reinterpret_cast<float2*>(&g_S[(size_t)(rg + 8) * NR + cg]) = v1;
        }
    }

    // Off-diagonal: stage C in smem, write transpose to tile (j0, i0)
    if (i0 != j0) {
        __syncthreads();                        // all ldmatrix reads of sm done
        #pragma unroll
        for (int mi = 0; mi < 2; ++mi) {
            #pragma unroll
            for (int ni = 0; ni < 8; ++ni) {
                int r1 = wm * 32 + mi * 16 + gid;
                int cc = wn * 64 + ni * 8 + 2 * tig;
                *reinterpret_cast<float2*>(sm + taddr(r1, cc)) =
                    make_float2(c[mi][ni][0], c[mi][ni][1]);
                *reinterpret_cast<float2*>(sm + taddr(r1 + 8, cc)) =
                    make_float2(c[mi][ni][2], c[mi][ni][3]);
            }
        }
        __syncthreads();
        // thread t: output row (j0 + c2), cols [i0+rb, i0+rb+64)
        const int c2 = t >> 1, rb = (t & 1) * 64;
        #pragma unroll
        for (int ib = 0; ib < 64; ib += 4) {
            float v0 = *reinterpret_cast<float*>(sm + taddr(rb + ib + 0, c2));
            float v1 = *reinterpret_cast<float*>(sm + taddr(rb + ib + 1, c2));
            float v2 = *reinterpret_cast<float*>(sm + taddr(rb + ib + 2, c2));
            float v3 = *reinterpret_cast<float*>(sm + taddr(rb + ib + 3, c2));
            *reinterpret_cast<float4*>(&g_S[(size_t)(j0 + c2) * NR + i0 + rb + ib]) =
                make_float4(v0, v1, v2, v3);
        }
    }
}

// ===========================================================================
// Kernel 3: per-row loss. 256 threads/CTA, 16 elements/thread in registers.
// match_any-aggregated histogram + parallel warp-shuffle suffix scan.
// ===========================================================================
__global__ void __launch_bounds__(256) loss_kernel(float* __restrict__ out) {
    __shared__ float smax[8];
    __shared__ int   swc[8];
    __shared__ unsigned hist[256];
    __shared__ unsigned wt[8];
    __shared__ unsigned s_sel[2];
    __shared__ float r4[4][8];

    const int i = blockIdx.x, t = threadIdx.x, lane = t & 31, warp = t >> 5;
    const float4* S4 = reinterpret_cast<const float4*>(g_S + (size_t)i * NR);
    const int4* L4 = reinterpret_cast<const int4*>(g_lab);
    const int labi = g_lab[i];

    float a[16]; int lb[16];
    float m = -1e30f;
    #pragma unroll
    for (int c = 0; c < 4; ++c) {
        float4 v = S4[c * 256 + t];
        int4 l = L4[c * 256 + t];
        a[c*4+0] = v.x * TEMP_INV; a[c*4+1] = v.y * TEMP_INV;
        a[c*4+2] = v.z * TEMP_INV; a[c*4+3] = v.w * TEMP_INV;
        lb[c*4+0] = l.x; lb[c*4+1] = l.y; lb[c*4+2] = l.z; lb[c*4+3] = l.w;
        #pragma unroll
        for (int q = 0; q < 4; ++q) m = fmaxf(m, a[c*4+q]);
    }
    #pragma unroll
    for (int off = 16; off > 0; off >>= 1) m = fmaxf(m, __shfl_xor_sync(0xFFFFFFFFu, m, off));
    if (lane == 0) smax[warp] = m;
    __syncthreads();
    float M = smax[0];
    #pragma unroll
    for (int w = 1; w < 8; ++w) M = fmaxf(M, smax[w]);

    unsigned key[16];
    int cneg = 0;
    #pragma unroll
    for (int e = 0; e < 16; ++e) {
        float x = a[e] - M;
        if (lb[e] != labi) {
            x -= MARGIN_C;
            unsigned b = __float_as_uint(x);
            key[e] = (b & 0x80000000u) ? ~b : (b | 0x80000000u);
            cneg++;
        } else key[e] = 0u;
        a[e] = x;
    }
    #pragma unroll
    for (int off = 16; off > 0; off >>= 1) cneg += __shfl_xor_sync(0xFFFFFFFFu, cneg, off);
    if (lane == 0) swc[warp] = cneg;
    __syncthreads();
    int count_neg = 0;
    #pragma unroll
    for (int w = 0; w < 8; ++w) count_neg += swc[w];

    const bool selAll = (count_neg <= TOPK);
    unsigned pfx = 0, kr = TOPK;
    if (!selAll) {
        #pragma unroll
        for (int shift = 24; shift >= 0; shift -= 8) {
            hist[t] = 0u;
            __syncthreads();
            #pragma unroll
            for (int e = 0; e < 16; ++e) {
                unsigned k = key[e];
                bool match = (k != 0u) &&
                             ((shift == 24) || ((k >> (shift + 8)) == (pfx >> (shift + 8))));
                unsigned dig = (k >> shift) & 255u;
                unsigned mv = match ? dig : 0xFFFFFFFFu;
                unsigned mk = __match_any_sync(0xFFFFFFFFu, mv);
                if (match && lane == (__ffs(mk) - 1))
                    atomicAdd(&hist[dig], (unsigned)__popc(mk));
            }
            __syncthreads();
            unsigned c = hist[t];
            unsigned v = c;
            #pragma unroll
            for (int off = 1; off < 32; off <<= 1) {
                unsigned u = __shfl_down_sync(0xFFFFFFFFu, v, off);
                if (lane + off < 32) v += u;
            }
            if (lane == 0) wt[warp] = v;     // warp-total
            __syncthreads();
            unsigned hi = 0;
            #pragma unroll
            for (int w = 0; w < 8; ++w) if (w > warp) hi += wt[w];
            unsigned suf_in = v + hi, suf_ex = suf_in - c;
            if (suf_ex < kr && suf_in >= kr) { s_sel[0] = (unsigned)t; s_sel[1] = kr - suf_ex; }
            __syncthreads();
            pfx |= s_sel[0] << shift;
            kr = s_sel[1];
            __syncthreads();
        }
    }
    const unsigned keystar = pfx;
    const unsigned rsel = kr;

    float ep = 0.f, lp = 0.f, cp = 0.f, en = 0.f;
    #pragma unroll
    for (int e = 0; e < 16; ++e) {
        if (key[e] == 0u) { float ex = __expf(a[e]); ep += ex; lp += a[e]; cp += 1.f; }
        else if (selAll || key[e] > keystar) en += __expf(a[e]);
    }
    #pragma unroll
    for (int off = 16; off > 0; off >>= 1) {
        ep += __shfl_xor_sync(0xFFFFFFFFu, ep, off);
        lp += __shfl_xor_sync(0xFFFFFFFFu, lp, off);
        cp += __shfl_xor_sync(0xFFFFFFFFu, cp, off);
        en += __shfl_xor_sync(0xFFFFFFFFu, en, off);
    }
    if (lane == 0) { r4[0][warp] = ep; r4[1][warp] = lp; r4[2][warp] = cp; r4[3][warp] = en; }
    __syncthreads();
    if (t == 0) {
        float Tep = 0, Tlp = 0, Tcp = 0, Ten = 0;
        #pragma unroll
        for (int w = 0; w < 8; ++w) { Tep += r4[0][w]; Tlp += r4[1][w]; Tcp += r4[2][w]; Ten += r4[3][w]; }
        if (!selAll) {
            unsigned b = (keystar & 0x80000000u) ? (keystar & 0x7FFFFFFFu) : ~keystar;
            Ten += (float)rsel * __expf(__uint_as_float(b));
        }
        float Z = Tep + Ten;
        float logZ = logf(Z + 1e-12f);
        float mlpp = (Tlp - Tcp * logZ) / (Tcp + 1e-12f);
        atomicAdd(out, LOSS_SCALE * mlpp * (1.0f / (float)NR));
    }
}

// ===========================================================================
extern "C" void kernel_launch(void* const* d_in, const int* in_sizes, int n_in,
                              void* d_out, int out_size) {
    const float* feat = (const float*)d_in[0];
    const long long* labels = (const long long*)d_in[1];
    float* out = (float*)d_out;

    cudaFuncSetAttribute(gemm_kernel, cudaFuncAttributeMaxDynamicSharedMemorySize, SMEM_GEMM);

    prep_kernel<<<NR, 256>>>(feat, labels, out);
    gemm_kernel<<<dim3(32, 32, 1), 256, SMEM_GEMM>>>();
    loss_kernel<<<NR, 256>>>(out);
}